// round 15
// baseline (speedup 1.0000x reference)
#include <cuda_runtime.h>
#include <stdint.h>
#include <math.h>

#define Bb 2
#define Tt 8
#define Cc 32
#define HW 4096
#define CHW (Cc*HW)
#define NBT (Bb*Tt)
#define NEL (NBT*CHW)         // 2097152
#define NTOK (NBT*HW)         // 65536

// ---------------- scratch (device globals; no allocation) ----------------
__device__ float g_xnc_r[NEL], g_xnc_i[NEL];
__device__ float g_conv[NBT*64*HW];
__device__ float g_z_r[NEL], g_z_i[NEL];
__device__ float g_znc_r[NEL], g_znc_i[NEL];
__device__ float g_x2_r[NEL], g_x2_i[NEL];
__device__ float g_ctxp[256*32];
__device__ float g_gain[NBT*Cc];
__device__ float2 g_evo[NBT*Cc];
__device__ float g_wT[9*64*64];       // [tap][ic][oc], tf32-rounded

// ---------------- tf32 / mma helpers ----------------
__device__ __forceinline__ float to_tf32(float x){
  float r; asm("cvt.rna.tf32.f32 %0, %1;" : "=f"(r) : "f"(x)); return r;
}
__device__ __forceinline__ void mma_tf32(float c[4], uint32_t a0, uint32_t a1,
                                         uint32_t a2, uint32_t a3,
                                         uint32_t b0, uint32_t b1){
  asm volatile("mma.sync.aligned.m16n8k8.row.col.f32.tf32.tf32.f32 "
    "{%0,%1,%2,%3}, {%4,%5,%6,%7}, {%8,%9}, {%0,%1,%2,%3};"
    : "+f"(c[0]), "+f"(c[1]), "+f"(c[2]), "+f"(c[3])
    : "r"(a0), "r"(a1), "r"(a2), "r"(a3), "r"(b0), "r"(b1));
}

// ---------------- threefry2x32 (JAX partitionable-mode compatible) ----------------
__host__ __device__ __forceinline__ uint32_t tf_rotl(uint32_t x, int r){ return (x<<r)|(x>>(32-r)); }
__host__ __device__ __forceinline__ void tf_block(uint32_t k0,uint32_t k1,uint32_t x0,uint32_t x1,
                                                  uint32_t* o0,uint32_t* o1){
  uint32_t ks2 = k0 ^ k1 ^ 0x1BD11BDAu;
  x0 += k0; x1 += k1;
#define R4(a,b,c,d) x0+=x1; x1=tf_rotl(x1,a); x1^=x0; x0+=x1; x1=tf_rotl(x1,b); x1^=x0; \
                    x0+=x1; x1=tf_rotl(x1,c); x1^=x0; x0+=x1; x1=tf_rotl(x1,d); x1^=x0;
  R4(13,15,26,6)  x0+=k1;  x1+=ks2+1u;
  R4(17,29,16,24) x0+=ks2; x1+=k0+2u;
  R4(13,15,26,6)  x0+=k0;  x1+=k1+3u;
  R4(17,29,16,24) x0+=k1;  x1+=ks2+4u;
  R4(13,15,26,6)  x0+=ks2; x1+=k0+5u;
#undef R4
  *o0=x0; *o1=x1;
}

__device__ __forceinline__ float tf_normal(uint32_t k0, uint32_t k1, uint32_t j){
  uint32_t o0,o1;
  tf_block(k0,k1, 0u, j, &o0,&o1);
  uint32_t bits = o0 ^ o1;
  const float lo = -0.99999994f;
  float f = __uint_as_float((bits>>9) | 0x3f800000u) - 1.0f;
  float u = f * (1.0f - lo) + lo;
  u = fmaxf(lo, u);
  return 1.41421356237309515f * erfinvf(u);
}

// ---------------- K0: weight transpose + tf32 round ----------------
__global__ void k_wprep(const float* __restrict__ cw){
  int i = blockIdx.x*256 + threadIdx.x;
  if (i >= 9*64*64) return;
  int tap = i >> 12, rem = i & 4095, ic = rem >> 6, oc = rem & 63;
  g_wT[i] = to_tf32(cw[((size_t)oc*64 + ic)*9 + tap]);
}

// ---------------- K1: spatial complex layernorm (2 px / thread, 128-thr blocks) ----------------
__global__ void k_ln_spatial(const float* __restrict__ xr, const float* __restrict__ xi,
                             const float* __restrict__ lg, const float* __restrict__ lb){
  int idx = blockIdx.x*128 + threadIdx.x;
  int bt = idx >> 11, p2 = idx & 2047;
  size_t base = (size_t)bt*CHW + p2*2;
  float s0=0.f,s1=0.f,q0=0.f,q1=0.f;
  #pragma unroll 8
  for (int c=0;c<Cc;c++){
    float2 r = *(const float2*)&xr[base + (size_t)c*HW];
    float2 im = *(const float2*)&xi[base + (size_t)c*HW];
    s0 += r.x + im.x; s1 += r.y + im.y;
    q0 += r.x*r.x + im.x*im.x; q1 += r.y*r.y + im.y*im.y;
  }
  float m0 = s0*(1.f/64.f), m1 = s1*(1.f/64.f);
  float i0 = rsqrtf(q0*(1.f/64.f) - m0*m0 + 1e-5f);
  float i1 = rsqrtf(q1*(1.f/64.f) - m1*m1 + 1e-5f);
  #pragma unroll 8
  for (int c=0;c<Cc;c++){
    float2 r = *(const float2*)&xr[base + (size_t)c*HW];
    float2 im = *(const float2*)&xi[base + (size_t)c*HW];
    float gr = lg[c], br = lb[c], gi = lg[c+32], bi = lb[c+32];
    *(float2*)&g_xnc_r[base + (size_t)c*HW] = make_float2((r.x-m0)*i0*gr+br, (r.y-m1)*i1*gr+br);
    *(float2*)&g_xnc_i[base + (size_t)c*HW] = make_float2((im.x-m0)*i0*gi+bi, (im.y-m1)*i1*gi+bi);
  }
}

// ---------------- K2: Clifford 3x3 conv — implicit GEMM, 512 thr (N split across warp halves) ----------------
// smem: Ain[32][264] + Bw[2][32][72] = 52224 B
#define CONV_SMEM_FLOATS (32*264 + 2*32*72)
__global__ void __launch_bounds__(512) k_conv(const float* __restrict__ cb){
  extern __shared__ float cs[];
  float* Ain = cs;             // [icl][rr=4][cc=66], tf32-rounded
  float* Bw  = cs + 32*264;    // [2][icl][72]
  int y0 = blockIdx.x*2, bt = blockIdx.y;
  int tid = threadIdx.x, lane = tid & 31, w = tid >> 5;   // 16 warps
  int half = w >> 3;            // 0: oc 0..31, 1: oc 32..63
  int wl = w & 7;
  int y_local = wl >> 2, x0 = (wl & 3)*16;
  int lm = lane >> 2, lk = lane & 3;

  float acc[4][4];
  #pragma unroll
  for (int nt=0;nt<4;nt++)
    #pragma unroll
    for (int j=0;j<4;j++) acc[nt][j] = 0.f;

  for (int chunk=0; chunk<2; chunk++){
    __syncthreads();     // previous chunk's Ain/Bw reads complete
    const float* pl = (chunk == 0 ? g_xnc_r : g_xnc_i) + (size_t)bt*CHW;
    for (int idx=tid; idx<32*264; idx+=512){
      int icl = idx/264, rem = idx - icl*264, rr = rem/66, cc = rem - rr*66;
      int gy = y0 - 1 + rr, gx = cc - 1;
      float v = (gy>=0 && gy<64 && gx>=0 && gx<64) ? pl[(size_t)icl*HW + gy*64+gx] : 0.f;
      Ain[idx] = to_tf32(v);
    }
    // preload tap0 weights
    for (int idx=tid; idx<2048; idx+=512){
      int icl = idx >> 6, oc = idx & 63;
      Bw[icl*72 + oc] = g_wT[(chunk*32 + icl)*64 + oc];
    }
    __syncthreads();
    for (int tap=0; tap<9; tap++){
      const float* BwC = Bw + (tap & 1)*(32*72);
      if (tap < 8){
        float* BwN = Bw + ((tap+1) & 1)*(32*72);
        for (int idx=tid; idx<2048; idx+=512){
          int icl = idx >> 6, oc = idx & 63;
          BwN[icl*72 + oc] = g_wT[((tap+1) << 12) + (chunk*32 + icl)*64 + oc];
        }
      }
      int rr = y_local + tap/3;
      int ccb = x0 + (tap - (tap/3)*3) + lm;
      #pragma unroll
      for (int ch=0; ch<4; ch++){
        const float* ap = &Ain[(ch*8 + lk)*264 + rr*66 + ccb];
        uint32_t a0 = __float_as_uint(ap[0]);
        uint32_t a1 = __float_as_uint(ap[8]);
        uint32_t a2 = __float_as_uint(ap[4*264]);
        uint32_t a3 = __float_as_uint(ap[4*264 + 8]);
        const float* bp = &BwC[(ch*8 + lk)*72 + half*32 + lm];
        #pragma unroll
        for (int nt=0; nt<4; nt++){
          uint32_t b0 = __float_as_uint(bp[nt*8]);
          uint32_t b1 = __float_as_uint(bp[4*72 + nt*8]);
          mma_tf32(acc[nt], a0, a1, a2, a3, b0, b1);
        }
      }
      __syncthreads();   // BwC reads done; BwN visible
    }
  }
  int yy = y0 + y_local;
  int x = x0 + lm;
  #pragma unroll
  for (int nt=0; nt<4; nt++){
    int oc = half*32 + nt*8 + 2*lk;
    float bv0 = cb[oc], bv1 = cb[oc+1];
    size_t o0 = (((size_t)bt*64 + oc)*64 + yy)*64;
    g_conv[o0 + x]            = acc[nt][0] + bv0;
    g_conv[o0 + 4096 + x]     = acc[nt][1] + bv1;
    g_conv[o0 + x + 8]        = acc[nt][2] + bv0;
    g_conv[o0 + 4096 + x + 8] = acc[nt][3] + bv1;
  }
}

// ---------------- K3: spectral branch (512 thr, fused col fwd->filter->inv, combine+residual) ----------------
__device__ __forceinline__ float2 cmul(float2 a, float2 b){
  return make_float2(a.x*b.x - a.y*b.y, a.x*b.y + a.y*b.x);
}
__device__ __forceinline__ void fft8(float2 a[8], float sgn){
  const float C1 = 0.70710678118654752440f;
  float2 w1 = make_float2(C1, sgn*C1);
  float2 w2 = make_float2(0.f, sgn);
  float2 w3 = make_float2(-C1, sgn*C1);
  float2 t;
  t = make_float2(a[0].x-a[4].x, a[0].y-a[4].y); a[0].x+=a[4].x; a[0].y+=a[4].y; a[4]=t;
  t = make_float2(a[1].x-a[5].x, a[1].y-a[5].y); a[1].x+=a[5].x; a[1].y+=a[5].y; a[5]=cmul(t,w1);
  t = make_float2(a[2].x-a[6].x, a[2].y-a[6].y); a[2].x+=a[6].x; a[2].y+=a[6].y; a[6]=cmul(t,w2);
  t = make_float2(a[3].x-a[7].x, a[3].y-a[7].y); a[3].x+=a[7].x; a[3].y+=a[7].y; a[7]=cmul(t,w3);
  #pragma unroll
  for (int g=0; g<8; g+=4){
    t = make_float2(a[g].x-a[g+2].x, a[g].y-a[g+2].y); a[g].x+=a[g+2].x; a[g].y+=a[g+2].y; a[g+2]=t;
    t = make_float2(a[g+1].x-a[g+3].x, a[g+1].y-a[g+3].y); a[g+1].x+=a[g+3].x; a[g+1].y+=a[g+3].y; a[g+3]=cmul(t,w2);
  }
  #pragma unroll
  for (int p=0; p<8; p+=2){
    t = make_float2(a[p].x-a[p+1].x, a[p].y-a[p+1].y); a[p].x+=a[p+1].x; a[p].y+=a[p+1].y; a[p+1]=t;
  }
}
__device__ __forceinline__ void fft64_line(float2* p, int st, int b8,
                                           const float2* __restrict__ tw, float sgn, bool conj_tw){
  const int rev[8] = {0,4,2,6,1,5,3,7};
  float2 a[8];
  #pragma unroll
  for (int j=0;j<8;j++) a[j] = p[(8*j + b8)*st];
  fft8(a, sgn);
  #pragma unroll
  for (int c=0;c<8;c++){
    float2 t = tw[(b8*c) & 63];
    if (conj_tw) t.y = -t.y;
    p[(8*c + b8)*st] = cmul(a[rev[c]], t);
  }
  __syncwarp();
  #pragma unroll
  for (int j=0;j<8;j++) a[j] = p[(8*b8 + j)*st];
  fft8(a, sgn);
  __syncwarp();
  #pragma unroll
  for (int d=0;d<8;d++) p[(b8 + 8*d)*st] = a[rev[d]];
  __syncwarp();
}

__device__ __forceinline__ void fft64_col_fused(float2* p, int b8,
                                                const float2* __restrict__ tw,
                                                const float* __restrict__ swr,
                                                const float* __restrict__ swi,
                                                int col){
  const int rev[8] = {0,4,2,6,1,5,3,7};
  float2 a[8];
  #pragma unroll
  for (int j=0;j<8;j++) a[j] = p[(8*j + b8)*65];
  fft8(a, -1.f);
  #pragma unroll
  for (int c=0;c<8;c++)
    p[(8*c + b8)*65] = cmul(a[rev[c]], tw[(b8*c) & 63]);
  __syncwarp();
  #pragma unroll
  for (int j=0;j<8;j++) a[j] = p[(8*b8 + j)*65];
  fft8(a, -1.f);
  float2 f[8];
  #pragma unroll
  for (int j=0;j<8;j++){
    int row = 8*j + b8;
    float2 wv = make_float2(swr[row*64 + col], swi[row*64 + col]);
    f[j] = cmul(a[rev[j]], wv);
  }
  fft8(f, 1.f);
  #pragma unroll
  for (int c=0;c<8;c++){
    float2 t = tw[(b8*c) & 63]; t.y = -t.y;
    p[(8*c + b8)*65] = cmul(f[rev[c]], t);
  }
  __syncwarp();
  #pragma unroll
  for (int j=0;j<8;j++) a[j] = p[(8*b8 + j)*65];
  fft8(a, 1.f);
  __syncwarp();
  #pragma unroll
  for (int d=0;d<8;d++) p[(b8 + 8*d)*65] = a[rev[d]];
  __syncwarp();
}

__global__ void __launch_bounds__(512) k_spec(
                       const float* __restrict__ swr, const float* __restrict__ swi,
                       const float* __restrict__ gate_p,
                       const float* __restrict__ xr, const float* __restrict__ xi){
  __shared__ float2 sm[64*65];
  __shared__ float2 tw[64];
  int blk = blockIdx.x; int bt = blk >> 5; int c = blk & 31;
  int tid = threadIdx.x;
  if (tid < 64){
    float sv, cv; sincosf(-6.283185307179586f * (float)tid / 64.f, &sv, &cv);
    tw[tid] = make_float2(cv, sv);
  }
  size_t base = ((size_t)bt*Cc + c)*HW;
  for (int i=tid;i<HW;i+=512)
    sm[(i>>6)*65 + (i&63)] = make_float2(g_xnc_r[base+i], g_xnc_i[base+i]);
  __syncthreads();
  int oct = tid >> 3, b8 = tid & 7;   // 64 groups, one line each
  fft64_line(sm + oct*65, 1, b8, tw, -1.f, false);
  __syncthreads();
  const float* swrc = swr + (size_t)c*HW;
  const float* swic = swi + (size_t)c*HW;
  fft64_col_fused(sm + oct, b8, tw, swrc, swic, oct);
  __syncthreads();
  fft64_line(sm + oct*65, 1, b8, tw, 1.f, true);
  __syncthreads();
  float g = gate_p[0];
  const float invN = 1.f/4096.f;
  for (int i=tid;i<HW;i+=512){
    float2 sp = sm[(i>>6)*65 + (i&63)];
    float cr = g_conv[((size_t)bt*64 + c)*HW + i];
    float ci = g_conv[((size_t)bt*64 + 32 + c)*HW + i];
    g_z_r[base+i] = g*cr + (1.f-g)*(sp.x*invN) + xr[base+i];
    g_z_i[base+i] = g*ci + (1.f-g)*(sp.y*invN) + xi[base+i];
  }
}

// ---------------- K4: temporal layernorm + ctx partials (2 px / thread, 128-thr blocks) ----------------
__global__ void k_ln_temporal(const float* __restrict__ lg, const float* __restrict__ lb){
  __shared__ float cacc2[4][32];
  int idx = blockIdx.x*128 + threadIdx.x;
  int bt = idx >> 11, p2 = idx & 2047;
  size_t base = (size_t)bt*CHW + p2*2;
  float s0=0.f,s1=0.f,q0=0.f,q1=0.f;
  #pragma unroll 8
  for (int c=0;c<Cc;c++){
    float2 r = *(const float2*)&g_z_r[base + (size_t)c*HW];
    float2 im = *(const float2*)&g_z_i[base + (size_t)c*HW];
    s0 += r.x + im.x; s1 += r.y + im.y;
    q0 += r.x*r.x + im.x*im.x; q1 += r.y*r.y + im.y*im.y;
  }
  float m0 = s0*(1.f/64.f), m1 = s1*(1.f/64.f);
  float i0 = rsqrtf(q0*(1.f/64.f) - m0*m0 + 1e-5f);
  float i1 = rsqrtf(q1*(1.f/64.f) - m1*m1 + 1e-5f);
  int lane = threadIdx.x & 31, wid = threadIdx.x >> 5;
  for (int c=0;c<Cc;c++){
    float2 r = *(const float2*)&g_z_r[base + (size_t)c*HW];
    float2 im = *(const float2*)&g_z_i[base + (size_t)c*HW];
    float gr = lg[c], br = lb[c], gi = lg[c+32], bi = lb[c+32];
    float nr0 = (r.x-m0)*i0*gr+br, nr1 = (r.y-m1)*i1*gr+br;
    float ni0 = (im.x-m0)*i0*gi+bi, ni1 = (im.y-m1)*i1*gi+bi;
    *(float2*)&g_znc_r[base + (size_t)c*HW] = make_float2(nr0, nr1);
    *(float2*)&g_znc_i[base + (size_t)c*HW] = make_float2(ni0, ni1);
    float mag = sqrtf(nr0*nr0 + ni0*ni0) + sqrtf(nr1*nr1 + ni1*ni1);
    #pragma unroll
    for (int off=16; off; off>>=1) mag += __shfl_xor_sync(0xffffffffu, mag, off);
    if (lane == 0) cacc2[wid][c] = mag;
  }
  __syncthreads();
  if (threadIdx.x < 32){
    float s = 0.f;
    #pragma unroll
    for (int w=0; w<4; w++) s += cacc2[w][threadIdx.x];
    g_ctxp[blockIdx.x*32 + threadIdx.x] = s;    // blockIdx = bt*16 + sub
  }
}

// ---------------- K5: evo + input gain (small) ----------------
__global__ void k_gates(const float* __restrict__ dt, const float* __restrict__ alpha,
                        const float* __restrict__ omega, const float* __restrict__ gW,
                        const float* __restrict__ gb){
  int i = threadIdx.x; if (i >= NBT*Cc) return;
  int bt = i >> 5, c = i & 31;
  float dtv = dt[bt];
  float a = alpha[c];
  float sp = (a > 0.f) ? a + log1pf(expf(-a)) : log1pf(expf(a));
  float er = expf(-dtv*sp);
  float sn, cs; sincosf(dtv*omega[c], &sn, &cs);
  g_evo[i] = make_float2(er*cs, er*sn);
  float acc = gb[c];
  for (int k=0;k<32;k++){
    float ctx = 0.f;
    for (int sb=0; sb<16; sb++) ctx += g_ctxp[(bt*16+sb)*32 + k];
    acc += (ctx * (1.f/4096.f)) * gW[k*32 + c];
  }
  g_gain[i] = 1.f/(1.f + expf(-acc));
}

// ---------------- K6: time scan + inline 4-chain threefry noise + residual (2 px / thread) ----------------
__global__ void k_scan(const float* __restrict__ dt, const float* __restrict__ sigma,
                       uint32_t k1a, uint32_t k1b, uint32_t k2a, uint32_t k2b){
  int gid = blockIdx.x*256 + threadIdx.x;          // Bb*Cc*2048 = 131072 threads
  int b = gid / (Cc*2048); int rem = gid - b*(Cc*2048);
  int c = rem >> 11; int pp = rem & 2047;
  size_t pbase = (size_t)pp*2;
  float2 hr = make_float2(0.f, 0.f), hi = make_float2(0.f, 0.f);
  float sg = sigma[c];
  #pragma unroll
  for (int t=0;t<Tt;t++){
    int btc = (b*Tt + t)*Cc + c;
    size_t base = (size_t)btc*HW + pbase;
    float2 e = g_evo[btc];
    float gn = g_gain[btc];
    float2 zr = *(const float2*)&g_znc_r[base];
    float2 zi = *(const float2*)&g_znc_i[base];
    float2 rr = *(const float2*)&g_z_r[base];
    float2 ri = *(const float2*)&g_z_i[base];
    float nr0 = tf_normal(k1a, k1b, (uint32_t)base);
    float nr1 = tf_normal(k1a, k1b, (uint32_t)base + 1u);
    float ni0 = tf_normal(k2a, k2b, (uint32_t)base);
    float ni1 = tf_normal(k2a, k2b, (uint32_t)base + 1u);
    float sc = sg * sqrtf(dt[b*Tt+t] + 1e-6f);
    float h0r = e.x*hr.x - e.y*hi.x + zr.x*gn;
    float h0i = e.x*hi.x + e.y*hr.x + zi.x*gn;
    float h1r = e.x*hr.y - e.y*hi.y + zr.y*gn;
    float h1i = e.x*hi.y + e.y*hr.y + zi.y*gn;
    hr = make_float2(h0r, h1r); hi = make_float2(h0i, h1i);
    *(float2*)&g_x2_r[base] = make_float2(h0r + sc*nr0 + rr.x, h1r + sc*nr1 + rr.y);
    *(float2*)&g_x2_i[base] = make_float2(h0i + sc*ni0 + ri.x, h1i + sc*ni1 + ri.y);
  }
}

// ---------------- K7: fused MLP on mma.sync tf32 ----------------
#define MLP_SMEM_FLOATS (64*136 + 64*136 + 64*72 + 64*72)
__global__ void k_mlp(const float* __restrict__ w1, const float* __restrict__ b1,
                      const float* __restrict__ w2, const float* __restrict__ b2,
                      float* __restrict__ out){
  extern __shared__ float smemf[];
  float* Xs  = smemf;                 // [k][m] pitch 136
  float* Hs  = smemf + 64*136;        // [k2][m] pitch 136
  float* Wc  = smemf + 2*64*136;      // [k][n] pitch 72
  float* Wc2 = smemf + 2*64*136 + 64*72;
  int m0 = blockIdx.x*128;
  int bt = m0 >> 12, px0 = m0 & 4095;
  int tid = threadIdx.x, lane = tid & 31, w = tid >> 5;
  int lm = lane >> 2, lk = lane & 3;
  int mbase = w*16;
  for (int idx=tid; idx<8192; idx+=256){
    int m = idx & 127, k = idx >> 7;
    const float* plane = (k < 32) ? g_x2_r : g_x2_i;
    Xs[k*136 + m] = to_tf32(plane[((size_t)bt*Cc + (k & 31))*HW + px0 + m]);
  }
  float oacc[8][4];
  #pragma unroll
  for (int nt=0;nt<8;nt++)
    #pragma unroll
    for (int j=0;j<4;j++) oacc[nt][j] = 0.f;

  for (int nc=0; nc<4; nc++){
    __syncthreads();
    for (int idx=tid; idx<4096; idx+=256){
      int n = idx & 63, k = idx >> 6;
      Wc[k*72 + n] = to_tf32(w1[(size_t)k*256 + nc*64 + n]);
    }
    for (int idx=tid; idx<4096; idx+=256){
      int n2 = idx & 63, k2 = idx >> 6;
      Wc2[k2*72 + n2] = to_tf32(w2[(size_t)(nc*64 + k2)*64 + n2]);
    }
    __syncthreads();
    float hacc[8][4];
    #pragma unroll
    for (int nt=0;nt<8;nt++)
      #pragma unroll
      for (int j=0;j<4;j++) hacc[nt][j] = 0.f;
    #pragma unroll
    for (int ch=0; ch<8; ch++){
      const float* ap = &Xs[(ch*8 + lk)*136 + mbase + lm];
      uint32_t a0 = __float_as_uint(ap[0]);
      uint32_t a1 = __float_as_uint(ap[8]);
      uint32_t a2 = __float_as_uint(ap[4*136]);
      uint32_t a3 = __float_as_uint(ap[4*136 + 8]);
      const float* bp = &Wc[(ch*8 + lk)*72 + lm];
      #pragma unroll
      for (int nt=0; nt<8; nt++){
        uint32_t b0 = __float_as_uint(bp[nt*8]);
        uint32_t b1 = __float_as_uint(bp[4*72 + nt*8]);
        mma_tf32(hacc[nt], a0, a1, a2, a3, b0, b1);
      }
    }
    #pragma unroll
    for (int nt=0; nt<8; nt++){
      int n = nt*8 + 2*lk;
      float bb0 = b1[nc*64 + n], bb1 = b1[nc*64 + n + 1];
      #pragma unroll
      for (int j=0;j<4;j++){
        float v = hacc[nt][j] + ((j & 1) ? bb1 : bb0);
        float gl = 0.5f*v*(1.f + tanhf(0.7978845608028654f*(v + 0.044715f*v*v*v)));
        int nn = n + (j & 1);
        int mm = mbase + lm + ((j >> 1) ? 8 : 0);
        Hs[nn*136 + mm] = to_tf32(gl);
      }
    }
    __syncthreads();
    #pragma unroll
    for (int ch=0; ch<8; ch++){
      const float* ap = &Hs[(ch*8 + lk)*136 + mbase + lm];
      uint32_t a0 = __float_as_uint(ap[0]);
      uint32_t a1 = __float_as_uint(ap[8]);
      uint32_t a2 = __float_as_uint(ap[4*136]);
      uint32_t a3 = __float_as_uint(ap[4*136 + 8]);
      const float* bp = &Wc2[(ch*8 + lk)*72 + lm];
      #pragma unroll
      for (int nt=0; nt<8; nt++){
        uint32_t b0 = __float_as_uint(bp[nt*8]);
        uint32_t b1 = __float_as_uint(bp[4*72 + nt*8]);
        mma_tf32(oacc[nt], a0, a1, a2, a3, b0, b1);
      }
    }
  }
  #pragma unroll
  for (int nt=0; nt<8; nt++){
    int n = nt*8 + 2*lk;
    float bb0 = b2[n], bb1 = b2[n+1];
    #pragma unroll
    for (int j=0;j<4;j++){
      int nn = n + (j & 1);
      int mm = mbase + lm + ((j >> 1) ? 8 : 0);
      int m = px0 + mm;
      float res = (nn < 32) ? g_x2_r[((size_t)bt*Cc + nn)*HW + m]
                            : g_x2_i[((size_t)bt*Cc + (nn-32))*HW + m];
      out[((size_t)bt*64 + nn)*HW + m] = oacc[nt][j] + ((j & 1) ? bb1 : bb0) + res;
    }
  }
}

// ---------------- host launcher ----------------
extern "C" void kernel_launch(void* const* d_in, const int* in_sizes, int n_in,
                              void* d_out, int out_size){
  const float* x_real = (const float*)d_in[0];
  const float* x_imag = (const float*)d_in[1];
  const float* dt     = (const float*)d_in[2];
  const float* ln_s_g = (const float*)d_in[3];
  const float* ln_s_b = (const float*)d_in[4];
  const float* cliffw = (const float*)d_in[5];
  const float* cliffb = (const float*)d_in[6];
  const float* specwr = (const float*)d_in[7];
  const float* specwi = (const float*)d_in[8];
  const float* gate   = (const float*)d_in[9];
  const float* ln_t_g = (const float*)d_in[10];
  const float* ln_t_b = (const float*)d_in[11];
  const float* alpha  = (const float*)d_in[12];
  const float* omega  = (const float*)d_in[13];
  const float* gain_W = (const float*)d_in[14];
  const float* gain_b = (const float*)d_in[15];
  const float* sigma  = (const float*)d_in[16];
  const float* pw1    = (const float*)d_in[17];
  const float* pb1    = (const float*)d_in[18];
  const float* pw2    = (const float*)d_in[19];
  const float* pb2    = (const float*)d_in[20];
  float* out = (float*)d_out;

  uint32_t k1a,k1b,k2a,k2b;
  tf_block(0u, 42u, 0u, 0u, &k1a, &k1b);   // keys[0]
  tf_block(0u, 42u, 0u, 1u, &k2a, &k2b);   // keys[1]

  static int smem_set = 0;
  if (!smem_set){
    cudaFuncSetAttribute(k_mlp, cudaFuncAttributeMaxDynamicSharedMemorySize,
                         MLP_SMEM_FLOATS*4);
    cudaFuncSetAttribute(k_conv, cudaFuncAttributeMaxDynamicSharedMemorySize,
                         CONV_SMEM_FLOATS*4);
    cudaFuncSetAttribute(k_conv, cudaFuncAttributePreferredSharedMemoryCarveout, 100);
    cudaFuncSetAttribute(k_spec, cudaFuncAttributePreferredSharedMemoryCarveout, 100);
    smem_set = 1;
  }

  k_wprep<<<144, 256>>>(cliffw);
  k_ln_spatial<<<256, 128>>>(x_real, x_imag, ln_s_g, ln_s_b);
  k_conv<<<dim3(32, 16), 512, CONV_SMEM_FLOATS*4>>>(cliffb);
  k_spec<<<512, 512>>>(specwr, specwi, gate, x_real, x_imag);
  k_ln_temporal<<<256, 128>>>(ln_t_g, ln_t_b);
  k_gates<<<1, 512>>>(dt, alpha, omega, gain_W, gain_b);
  k_scan<<<512, 256>>>(dt, sigma, k1a, k1b, k2a, k2b);
  k_mlp<<<512, 256, MLP_SMEM_FLOATS*4>>>(pw1, pb1, pw2, pb2, out);
}

// round 16
// speedup vs baseline: 1.1652x; 1.1652x over previous
#include <cuda_runtime.h>
#include <stdint.h>
#include <math.h>

#define Bb 2
#define Tt 8
#define Cc 32
#define HW 4096
#define CHW (Cc*HW)
#define NBT (Bb*Tt)
#define NEL (NBT*CHW)         // 2097152
#define NTOK (NBT*HW)         // 65536

// ---------------- scratch (device globals; no allocation) ----------------
__device__ float g_xnc_r[NEL], g_xnc_i[NEL];
__device__ float g_conv[NBT*64*HW];
__device__ float g_z_r[NEL], g_z_i[NEL];
__device__ float g_znc_r[NEL], g_znc_i[NEL];
__device__ float g_x2_r[NEL], g_x2_i[NEL];
__device__ float g_ctxp[256*32];
__device__ float g_gain[NBT*Cc];
__device__ float2 g_evo[NBT*Cc];
__device__ float g_wT[9*64*64];       // [tap][ic][oc], tf32-rounded

// ---------------- tf32 / mma helpers ----------------
__device__ __forceinline__ float to_tf32(float x){
  float r; asm("cvt.rna.tf32.f32 %0, %1;" : "=f"(r) : "f"(x)); return r;
}
__device__ __forceinline__ void mma_tf32(float c[4], uint32_t a0, uint32_t a1,
                                         uint32_t a2, uint32_t a3,
                                         uint32_t b0, uint32_t b1){
  asm volatile("mma.sync.aligned.m16n8k8.row.col.f32.tf32.tf32.f32 "
    "{%0,%1,%2,%3}, {%4,%5,%6,%7}, {%8,%9}, {%0,%1,%2,%3};"
    : "+f"(c[0]), "+f"(c[1]), "+f"(c[2]), "+f"(c[3])
    : "r"(a0), "r"(a1), "r"(a2), "r"(a3), "r"(b0), "r"(b1));
}

// ---------------- threefry2x32 (JAX partitionable-mode compatible) ----------------
__host__ __device__ __forceinline__ uint32_t tf_rotl(uint32_t x, int r){ return (x<<r)|(x>>(32-r)); }
__host__ __device__ __forceinline__ void tf_block(uint32_t k0,uint32_t k1,uint32_t x0,uint32_t x1,
                                                  uint32_t* o0,uint32_t* o1){
  uint32_t ks2 = k0 ^ k1 ^ 0x1BD11BDAu;
  x0 += k0; x1 += k1;
#define R4(a,b,c,d) x0+=x1; x1=tf_rotl(x1,a); x1^=x0; x0+=x1; x1=tf_rotl(x1,b); x1^=x0; \
                    x0+=x1; x1=tf_rotl(x1,c); x1^=x0; x0+=x1; x1=tf_rotl(x1,d); x1^=x0;
  R4(13,15,26,6)  x0+=k1;  x1+=ks2+1u;
  R4(17,29,16,24) x0+=ks2; x1+=k0+2u;
  R4(13,15,26,6)  x0+=k0;  x1+=k1+3u;
  R4(17,29,16,24) x0+=k1;  x1+=ks2+4u;
  R4(13,15,26,6)  x0+=ks2; x1+=k0+5u;
#undef R4
  *o0=x0; *o1=x1;
}

__device__ __forceinline__ float tf_normal(uint32_t k0, uint32_t k1, uint32_t j){
  uint32_t o0,o1;
  tf_block(k0,k1, 0u, j, &o0,&o1);
  uint32_t bits = o0 ^ o1;
  const float lo = -0.99999994f;
  float f = __uint_as_float((bits>>9) | 0x3f800000u) - 1.0f;
  float u = f * (1.0f - lo) + lo;
  u = fmaxf(lo, u);
  return 1.41421356237309515f * erfinvf(u);
}

// ---------------- K0: weight transpose + tf32 round ----------------
__global__ void k_wprep(const float* __restrict__ cw){
  int i = blockIdx.x*256 + threadIdx.x;
  if (i >= 9*64*64) return;
  int tap = i >> 12, rem = i & 4095, ic = rem >> 6, oc = rem & 63;
  g_wT[i] = to_tf32(cw[((size_t)oc*64 + ic)*9 + tap]);
}

// ---------------- K1: spatial LN — split-channel (lane halves), 64K threads ----------------
__global__ void k_ln_spatial(const float* __restrict__ xr, const float* __restrict__ xi,
                             const float* __restrict__ lg, const float* __restrict__ lb){
  int gtid = blockIdx.x*256 + threadIdx.x;
  int lane = threadIdx.x & 31;
  int halfc = (lane >> 4)*16;                 // 0 or 16
  int pp = (gtid >> 5)*16 + (lane & 15);      // pixel-pair id, 0..32767
  int bt = pp >> 11, p2 = pp & 2047;
  size_t base = (size_t)bt*CHW + p2*2;
  float s0=0.f,s1=0.f,q0=0.f,q1=0.f;
  #pragma unroll
  for (int cc=0;cc<16;cc++){
    int c = halfc + cc;
    float2 r = *(const float2*)&xr[base + (size_t)c*HW];
    float2 im = *(const float2*)&xi[base + (size_t)c*HW];
    s0 += r.x + im.x; s1 += r.y + im.y;
    q0 += r.x*r.x + im.x*im.x; q1 += r.y*r.y + im.y*im.y;
  }
  s0 += __shfl_xor_sync(0xffffffffu, s0, 16);
  s1 += __shfl_xor_sync(0xffffffffu, s1, 16);
  q0 += __shfl_xor_sync(0xffffffffu, q0, 16);
  q1 += __shfl_xor_sync(0xffffffffu, q1, 16);
  float m0 = s0*(1.f/64.f), m1 = s1*(1.f/64.f);
  float i0 = rsqrtf(q0*(1.f/64.f) - m0*m0 + 1e-5f);
  float i1 = rsqrtf(q1*(1.f/64.f) - m1*m1 + 1e-5f);
  #pragma unroll
  for (int cc=0;cc<16;cc++){
    int c = halfc + cc;
    float2 r = *(const float2*)&xr[base + (size_t)c*HW];
    float2 im = *(const float2*)&xi[base + (size_t)c*HW];
    float gr = lg[c], br = lb[c], gi = lg[c+32], bi = lb[c+32];
    *(float2*)&g_xnc_r[base + (size_t)c*HW] = make_float2((r.x-m0)*i0*gr+br, (r.y-m1)*i1*gr+br);
    *(float2*)&g_xnc_i[base + (size_t)c*HW] = make_float2((im.x-m0)*i0*gi+bi, (im.y-m1)*i1*gi+bi);
  }
}

// ---------------- K2: Clifford 3x3 conv — implicit GEMM, ic-chunked, Bw double-buffered (R13) ----------------
#define CONV_SMEM_FLOATS (32*264 + 2*32*72)
__global__ void __launch_bounds__(256, 4) k_conv(const float* __restrict__ cb){
  extern __shared__ float cs[];
  float* Ain = cs;             // [icl][rr=4][cc=66], tf32-rounded
  float* Bw  = cs + 32*264;    // [2][icl][72]
  int y0 = blockIdx.x*2, bt = blockIdx.y;
  int tid = threadIdx.x, lane = tid & 31, w = tid >> 5;
  int y_local = w >> 2, x0 = (w & 3)*16;
  int lm = lane >> 2, lk = lane & 3;

  float acc[8][4];
  #pragma unroll
  for (int nt=0;nt<8;nt++)
    #pragma unroll
    for (int j=0;j<4;j++) acc[nt][j] = 0.f;

  for (int chunk=0; chunk<2; chunk++){
    __syncthreads();
    const float* pl = (chunk == 0 ? g_xnc_r : g_xnc_i) + (size_t)bt*CHW;
    for (int idx=tid; idx<32*264; idx+=256){
      int icl = idx/264, rem = idx - icl*264, rr = rem/66, cc = rem - rr*66;
      int gy = y0 - 1 + rr, gx = cc - 1;
      float v = (gy>=0 && gy<64 && gx>=0 && gx<64) ? pl[(size_t)icl*HW + gy*64+gx] : 0.f;
      Ain[idx] = to_tf32(v);
    }
    for (int idx=tid; idx<2048; idx+=256){
      int icl = idx >> 6, oc = idx & 63;
      Bw[icl*72 + oc] = g_wT[(chunk*32 + icl)*64 + oc];
    }
    __syncthreads();
    for (int tap=0; tap<9; tap++){
      const float* BwC = Bw + (tap & 1)*(32*72);
      if (tap < 8){
        float* BwN = Bw + ((tap+1) & 1)*(32*72);
        for (int idx=tid; idx<2048; idx+=256){
          int icl = idx >> 6, oc = idx & 63;
          BwN[icl*72 + oc] = g_wT[((tap+1) << 12) + (chunk*32 + icl)*64 + oc];
        }
      }
      int rr = y_local + tap/3;
      int ccb = x0 + (tap - (tap/3)*3) + lm;
      #pragma unroll
      for (int ch=0; ch<4; ch++){
        const float* ap = &Ain[(ch*8 + lk)*264 + rr*66 + ccb];
        uint32_t a0 = __float_as_uint(ap[0]);
        uint32_t a1 = __float_as_uint(ap[8]);
        uint32_t a2 = __float_as_uint(ap[4*264]);
        uint32_t a3 = __float_as_uint(ap[4*264 + 8]);
        const float* bp = &BwC[(ch*8 + lk)*72 + lm];
        #pragma unroll
        for (int nt=0; nt<8; nt++){
          uint32_t b0 = __float_as_uint(bp[nt*8]);
          uint32_t b1 = __float_as_uint(bp[4*72 + nt*8]);
          mma_tf32(acc[nt], a0, a1, a2, a3, b0, b1);
        }
      }
      __syncthreads();
    }
  }
  int yy = y0 + y_local;
  int x = x0 + lm;
  #pragma unroll
  for (int nt=0; nt<8; nt++){
    int oc = nt*8 + 2*lk;
    float bv0 = cb[oc], bv1 = cb[oc+1];
    size_t o0 = (((size_t)bt*64 + oc)*64 + yy)*64;
    g_conv[o0 + x]            = acc[nt][0] + bv0;
    g_conv[o0 + 4096 + x]     = acc[nt][1] + bv1;
    g_conv[o0 + x + 8]        = acc[nt][2] + bv0;
    g_conv[o0 + 4096 + x + 8] = acc[nt][3] + bv1;
  }
}

// ---------------- K3: spectral branch (R13: 256 thr, fused col, combine+residual) ----------------
__device__ __forceinline__ float2 cmul(float2 a, float2 b){
  return make_float2(a.x*b.x - a.y*b.y, a.x*b.y + a.y*b.x);
}
__device__ __forceinline__ void fft8(float2 a[8], float sgn){
  const float C1 = 0.70710678118654752440f;
  float2 w1 = make_float2(C1, sgn*C1);
  float2 w2 = make_float2(0.f, sgn);
  float2 w3 = make_float2(-C1, sgn*C1);
  float2 t;
  t = make_float2(a[0].x-a[4].x, a[0].y-a[4].y); a[0].x+=a[4].x; a[0].y+=a[4].y; a[4]=t;
  t = make_float2(a[1].x-a[5].x, a[1].y-a[5].y); a[1].x+=a[5].x; a[1].y+=a[5].y; a[5]=cmul(t,w1);
  t = make_float2(a[2].x-a[6].x, a[2].y-a[6].y); a[2].x+=a[6].x; a[2].y+=a[6].y; a[6]=cmul(t,w2);
  t = make_float2(a[3].x-a[7].x, a[3].y-a[7].y); a[3].x+=a[7].x; a[3].y+=a[7].y; a[7]=cmul(t,w3);
  #pragma unroll
  for (int g=0; g<8; g+=4){
    t = make_float2(a[g].x-a[g+2].x, a[g].y-a[g+2].y); a[g].x+=a[g+2].x; a[g].y+=a[g+2].y; a[g+2]=t;
    t = make_float2(a[g+1].x-a[g+3].x, a[g+1].y-a[g+3].y); a[g+1].x+=a[g+3].x; a[g+1].y+=a[g+3].y; a[g+3]=cmul(t,w2);
  }
  #pragma unroll
  for (int p=0; p<8; p+=2){
    t = make_float2(a[p].x-a[p+1].x, a[p].y-a[p+1].y); a[p].x+=a[p+1].x; a[p].y+=a[p+1].y; a[p+1]=t;
  }
}
__device__ __forceinline__ void fft64_line(float2* p, int st, int b8,
                                           const float2* __restrict__ tw, float sgn, bool conj_tw){
  const int rev[8] = {0,4,2,6,1,5,3,7};
  float2 a[8];
  #pragma unroll
  for (int j=0;j<8;j++) a[j] = p[(8*j + b8)*st];
  fft8(a, sgn);
  #pragma unroll
  for (int c=0;c<8;c++){
    float2 t = tw[(b8*c) & 63];
    if (conj_tw) t.y = -t.y;
    p[(8*c + b8)*st] = cmul(a[rev[c]], t);
  }
  __syncwarp();
  #pragma unroll
  for (int j=0;j<8;j++) a[j] = p[(8*b8 + j)*st];
  fft8(a, sgn);
  __syncwarp();
  #pragma unroll
  for (int d=0;d<8;d++) p[(b8 + 8*d)*st] = a[rev[d]];
  __syncwarp();
}

__device__ __forceinline__ void fft64_col_fused(float2* p, int b8,
                                                const float2* __restrict__ tw,
                                                const float* __restrict__ swr,
                                                const float* __restrict__ swi,
                                                int col){
  const int rev[8] = {0,4,2,6,1,5,3,7};
  float2 a[8];
  #pragma unroll
  for (int j=0;j<8;j++) a[j] = p[(8*j + b8)*65];
  fft8(a, -1.f);
  #pragma unroll
  for (int c=0;c<8;c++)
    p[(8*c + b8)*65] = cmul(a[rev[c]], tw[(b8*c) & 63]);
  __syncwarp();
  #pragma unroll
  for (int j=0;j<8;j++) a[j] = p[(8*b8 + j)*65];
  fft8(a, -1.f);
  float2 f[8];
  #pragma unroll
  for (int j=0;j<8;j++){
    int row = 8*j + b8;
    float2 wv = make_float2(swr[row*64 + col], swi[row*64 + col]);
    f[j] = cmul(a[rev[j]], wv);
  }
  fft8(f, 1.f);
  #pragma unroll
  for (int c=0;c<8;c++){
    float2 t = tw[(b8*c) & 63]; t.y = -t.y;
    p[(8*c + b8)*65] = cmul(f[rev[c]], t);
  }
  __syncwarp();
  #pragma unroll
  for (int j=0;j<8;j++) a[j] = p[(8*b8 + j)*65];
  fft8(a, 1.f);
  __syncwarp();
  #pragma unroll
  for (int d=0;d<8;d++) p[(b8 + 8*d)*65] = a[rev[d]];
  __syncwarp();
}

__global__ void k_spec(const float* __restrict__ swr, const float* __restrict__ swi,
                       const float* __restrict__ gate_p,
                       const float* __restrict__ xr, const float* __restrict__ xi){
  __shared__ float2 sm[64*65];
  __shared__ float2 tw[64];
  int blk = blockIdx.x; int bt = blk >> 5; int c = blk & 31;
  int tid = threadIdx.x;
  if (tid < 64){
    float sv, cv; sincosf(-6.283185307179586f * (float)tid / 64.f, &sv, &cv);
    tw[tid] = make_float2(cv, sv);
  }
  size_t base = ((size_t)bt*Cc + c)*HW;
  for (int i=tid;i<HW;i+=256)
    sm[(i>>6)*65 + (i&63)] = make_float2(g_xnc_r[base+i], g_xnc_i[base+i]);
  __syncthreads();
  int oct = tid >> 3, b8 = tid & 7;
  for (int rep=0; rep<2; rep++) fft64_line(sm + (oct+32*rep)*65, 1, b8, tw, -1.f, false);
  __syncthreads();
  const float* swrc = swr + (size_t)c*HW;
  const float* swic = swi + (size_t)c*HW;
  for (int rep=0; rep<2; rep++){
    int col = oct + 32*rep;
    fft64_col_fused(sm + col, b8, tw, swrc, swic, col);
  }
  __syncthreads();
  for (int rep=0; rep<2; rep++) fft64_line(sm + (oct+32*rep)*65, 1, b8, tw, 1.f, true);
  __syncthreads();
  float g = gate_p[0];
  const float invN = 1.f/4096.f;
  for (int i=tid;i<HW;i+=256){
    float2 sp = sm[(i>>6)*65 + (i&63)];
    float cr = g_conv[((size_t)bt*64 + c)*HW + i];
    float ci = g_conv[((size_t)bt*64 + 32 + c)*HW + i];
    g_z_r[base+i] = g*cr + (1.f-g)*(sp.x*invN) + xr[base+i];
    g_z_i[base+i] = g*ci + (1.f-g)*(sp.y*invN) + xi[base+i];
  }
}

// ---------------- K4: temporal LN + ctx — split-channel (lane halves), 64K threads ----------------
__global__ void k_ln_temporal(const float* __restrict__ lg, const float* __restrict__ lb){
  __shared__ float cacc2[8][32];
  int gtid = blockIdx.x*256 + threadIdx.x;
  int lane = threadIdx.x & 31, wid = threadIdx.x >> 5;
  int halfc = (lane >> 4)*16;
  int pp = (gtid >> 5)*16 + (lane & 15);
  int bt = pp >> 11, p2 = pp & 2047;
  size_t base = (size_t)bt*CHW + p2*2;
  float s0=0.f,s1=0.f,q0=0.f,q1=0.f;
  #pragma unroll
  for (int cc=0;cc<16;cc++){
    int c = halfc + cc;
    float2 r = *(const float2*)&g_z_r[base + (size_t)c*HW];
    float2 im = *(const float2*)&g_z_i[base + (size_t)c*HW];
    s0 += r.x + im.x; s1 += r.y + im.y;
    q0 += r.x*r.x + im.x*im.x; q1 += r.y*r.y + im.y*im.y;
  }
  s0 += __shfl_xor_sync(0xffffffffu, s0, 16);
  s1 += __shfl_xor_sync(0xffffffffu, s1, 16);
  q0 += __shfl_xor_sync(0xffffffffu, q0, 16);
  q1 += __shfl_xor_sync(0xffffffffu, q1, 16);
  float m0 = s0*(1.f/64.f), m1 = s1*(1.f/64.f);
  float i0 = rsqrtf(q0*(1.f/64.f) - m0*m0 + 1e-5f);
  float i1 = rsqrtf(q1*(1.f/64.f) - m1*m1 + 1e-5f);
  #pragma unroll
  for (int cc=0;cc<16;cc++){
    int c = halfc + cc;
    float2 r = *(const float2*)&g_z_r[base + (size_t)c*HW];
    float2 im = *(const float2*)&g_z_i[base + (size_t)c*HW];
    float gr = lg[c], br = lb[c], gi = lg[c+32], bi = lb[c+32];
    float nr0 = (r.x-m0)*i0*gr+br, nr1 = (r.y-m1)*i1*gr+br;
    float ni0 = (im.x-m0)*i0*gi+bi, ni1 = (im.y-m1)*i1*gi+bi;
    *(float2*)&g_znc_r[base + (size_t)c*HW] = make_float2(nr0, nr1);
    *(float2*)&g_znc_i[base + (size_t)c*HW] = make_float2(ni0, ni1);
    float mag = sqrtf(nr0*nr0 + ni0*ni0) + sqrtf(nr1*nr1 + ni1*ni1);
    // reduce over the 16 pixel-lanes of this half (xor bits 0..3 stay in half)
    mag += __shfl_xor_sync(0xffffffffu, mag, 1);
    mag += __shfl_xor_sync(0xffffffffu, mag, 2);
    mag += __shfl_xor_sync(0xffffffffu, mag, 4);
    mag += __shfl_xor_sync(0xffffffffu, mag, 8);
    if ((lane & 15) == 0) cacc2[wid][c] = mag;
  }
  __syncthreads();
  if (threadIdx.x < 32){
    float s = 0.f;
    #pragma unroll
    for (int w=0; w<8; w++) s += cacc2[w][threadIdx.x];
    g_ctxp[blockIdx.x*32 + threadIdx.x] = s;    // 256 blocks = bt*16 + sub
  }
}

// ---------------- K5: evo + input gain (small) ----------------
__global__ void k_gates(const float* __restrict__ dt, const float* __restrict__ alpha,
                        const float* __restrict__ omega, const float* __restrict__ gW,
                        const float* __restrict__ gb){
  int i = threadIdx.x; if (i >= NBT*Cc) return;
  int bt = i >> 5, c = i & 31;
  float dtv = dt[bt];
  float a = alpha[c];
  float sp = (a > 0.f) ? a + log1pf(expf(-a)) : log1pf(expf(a));
  float er = expf(-dtv*sp);
  float sn, cs; sincosf(dtv*omega[c], &sn, &cs);
  g_evo[i] = make_float2(er*cs, er*sn);
  float acc = gb[c];
  for (int k=0;k<32;k++){
    float ctx = 0.f;
    for (int sb=0; sb<16; sb++) ctx += g_ctxp[(bt*16+sb)*32 + k];
    acc += (ctx * (1.f/4096.f)) * gW[k*32 + c];
  }
  g_gain[i] = 1.f/(1.f + expf(-acc));
}

// ---------------- K6: time scan + inline 4-chain threefry noise + residual (2 px / thread) ----------------
__global__ void k_scan(const float* __restrict__ dt, const float* __restrict__ sigma,
                       uint32_t k1a, uint32_t k1b, uint32_t k2a, uint32_t k2b){
  int gid = blockIdx.x*256 + threadIdx.x;          // Bb*Cc*2048 = 131072 threads
  int b = gid / (Cc*2048); int rem = gid - b*(Cc*2048);
  int c = rem >> 11; int pp = rem & 2047;
  size_t pbase = (size_t)pp*2;
  float2 hr = make_float2(0.f, 0.f), hi = make_float2(0.f, 0.f);
  float sg = sigma[c];
  #pragma unroll
  for (int t=0;t<Tt;t++){
    int btc = (b*Tt + t)*Cc + c;
    size_t base = (size_t)btc*HW + pbase;
    float2 e = g_evo[btc];
    float gn = g_gain[btc];
    float2 zr = *(const float2*)&g_znc_r[base];
    float2 zi = *(const float2*)&g_znc_i[base];
    float2 rr = *(const float2*)&g_z_r[base];
    float2 ri = *(const float2*)&g_z_i[base];
    float nr0 = tf_normal(k1a, k1b, (uint32_t)base);
    float nr1 = tf_normal(k1a, k1b, (uint32_t)base + 1u);
    float ni0 = tf_normal(k2a, k2b, (uint32_t)base);
    float ni1 = tf_normal(k2a, k2b, (uint32_t)base + 1u);
    float sc = sg * sqrtf(dt[b*Tt+t] + 1e-6f);
    float h0r = e.x*hr.x - e.y*hi.x + zr.x*gn;
    float h0i = e.x*hi.x + e.y*hr.x + zi.x*gn;
    float h1r = e.x*hr.y - e.y*hi.y + zr.y*gn;
    float h1i = e.x*hi.y + e.y*hr.y + zi.y*gn;
    hr = make_float2(h0r, h1r); hi = make_float2(h0i, h1i);
    *(float2*)&g_x2_r[base] = make_float2(h0r + sc*nr0 + rr.x, h1r + sc*nr1 + rr.y);
    *(float2*)&g_x2_i[base] = make_float2(h0i + sc*ni0 + ri.x, h1i + sc*ni1 + ri.y);
  }
}

// ---------------- K7: fused MLP on mma.sync tf32 ----------------
#define MLP_SMEM_FLOATS (64*136 + 64*136 + 64*72 + 64*72)
__global__ void k_mlp(const float* __restrict__ w1, const float* __restrict__ b1,
                      const float* __restrict__ w2, const float* __restrict__ b2,
                      float* __restrict__ out){
  extern __shared__ float smemf[];
  float* Xs  = smemf;                 // [k][m] pitch 136
  float* Hs  = smemf + 64*136;        // [k2][m] pitch 136
  float* Wc  = smemf + 2*64*136;      // [k][n] pitch 72
  float* Wc2 = smemf + 2*64*136 + 64*72;
  int m0 = blockIdx.x*128;
  int bt = m0 >> 12, px0 = m0 & 4095;
  int tid = threadIdx.x, lane = tid & 31, w = tid >> 5;
  int lm = lane >> 2, lk = lane & 3;
  int mbase = w*16;
  for (int idx=tid; idx<8192; idx+=256){
    int m = idx & 127, k = idx >> 7;
    const float* plane = (k < 32) ? g_x2_r : g_x2_i;
    Xs[k*136 + m] = to_tf32(plane[((size_t)bt*Cc + (k & 31))*HW + px0 + m]);
  }
  float oacc[8][4];
  #pragma unroll
  for (int nt=0;nt<8;nt++)
    #pragma unroll
    for (int j=0;j<4;j++) oacc[nt][j] = 0.f;

  for (int nc=0; nc<4; nc++){
    __syncthreads();
    for (int idx=tid; idx<4096; idx+=256){
      int n = idx & 63, k = idx >> 6;
      Wc[k*72 + n] = to_tf32(w1[(size_t)k*256 + nc*64 + n]);
    }
    for (int idx=tid; idx<4096; idx+=256){
      int n2 = idx & 63, k2 = idx >> 6;
      Wc2[k2*72 + n2] = to_tf32(w2[(size_t)(nc*64 + k2)*64 + n2]);
    }
    __syncthreads();
    float hacc[8][4];
    #pragma unroll
    for (int nt=0;nt<8;nt++)
      #pragma unroll
      for (int j=0;j<4;j++) hacc[nt][j] = 0.f;
    #pragma unroll
    for (int ch=0; ch<8; ch++){
      const float* ap = &Xs[(ch*8 + lk)*136 + mbase + lm];
      uint32_t a0 = __float_as_uint(ap[0]);
      uint32_t a1 = __float_as_uint(ap[8]);
      uint32_t a2 = __float_as_uint(ap[4*136]);
      uint32_t a3 = __float_as_uint(ap[4*136 + 8]);
      const float* bp = &Wc[(ch*8 + lk)*72 + lm];
      #pragma unroll
      for (int nt=0; nt<8; nt++){
        uint32_t b0 = __float_as_uint(bp[nt*8]);
        uint32_t b1 = __float_as_uint(bp[4*72 + nt*8]);
        mma_tf32(hacc[nt], a0, a1, a2, a3, b0, b1);
      }
    }
    #pragma unroll
    for (int nt=0; nt<8; nt++){
      int n = nt*8 + 2*lk;
      float bb0 = b1[nc*64 + n], bb1 = b1[nc*64 + n + 1];
      #pragma unroll
      for (int j=0;j<4;j++){
        float v = hacc[nt][j] + ((j & 1) ? bb1 : bb0);
        float gl = 0.5f*v*(1.f + tanhf(0.7978845608028654f*(v + 0.044715f*v*v*v)));
        int nn = n + (j & 1);
        int mm = mbase + lm + ((j >> 1) ? 8 : 0);
        Hs[nn*136 + mm] = to_tf32(gl);
      }
    }
    __syncthreads();
    #pragma unroll
    for (int ch=0; ch<8; ch++){
      const float* ap = &Hs[(ch*8 + lk)*136 + mbase + lm];
      uint32_t a0 = __float_as_uint(ap[0]);
      uint32_t a1 = __float_as_uint(ap[8]);
      uint32_t a2 = __float_as_uint(ap[4*136]);
      uint32_t a3 = __float_as_uint(ap[4*136 + 8]);
      const float* bp = &Wc2[(ch*8 + lk)*72 + lm];
      #pragma unroll
      for (int nt=0; nt<8; nt++){
        uint32_t b0 = __float_as_uint(bp[nt*8]);
        uint32_t b1 = __float_as_uint(bp[4*72 + nt*8]);
        mma_tf32(oacc[nt], a0, a1, a2, a3, b0, b1);
      }
    }
  }
  #pragma unroll
  for (int nt=0; nt<8; nt++){
    int n = nt*8 + 2*lk;
    float bb0 = b2[n], bb1 = b2[n+1];
    #pragma unroll
    for (int j=0;j<4;j++){
      int nn = n + (j & 1);
      int mm = mbase + lm + ((j >> 1) ? 8 : 0);
      int m = px0 + mm;
      float res = (nn < 32) ? g_x2_r[((size_t)bt*Cc + nn)*HW + m]
                            : g_x2_i[((size_t)bt*Cc + (nn-32))*HW + m];
      out[((size_t)bt*64 + nn)*HW + m] = oacc[nt][j] + ((j & 1) ? bb1 : bb0) + res;
    }
  }
}

// ---------------- host launcher ----------------
extern "C" void kernel_launch(void* const* d_in, const int* in_sizes, int n_in,
                              void* d_out, int out_size){
  const float* x_real = (const float*)d_in[0];
  const float* x_imag = (const float*)d_in[1];
  const float* dt     = (const float*)d_in[2];
  const float* ln_s_g = (const float*)d_in[3];
  const float* ln_s_b = (const float*)d_in[4];
  const float* cliffw = (const float*)d_in[5];
  const float* cliffb = (const float*)d_in[6];
  const float* specwr = (const float*)d_in[7];
  const float* specwi = (const float*)d_in[8];
  const float* gate   = (const float*)d_in[9];
  const float* ln_t_g = (const float*)d_in[10];
  const float* ln_t_b = (const float*)d_in[11];
  const float* alpha  = (const float*)d_in[12];
  const float* omega  = (const float*)d_in[13];
  const float* gain_W = (const float*)d_in[14];
  const float* gain_b = (const float*)d_in[15];
  const float* sigma  = (const float*)d_in[16];
  const float* pw1    = (const float*)d_in[17];
  const float* pb1    = (const float*)d_in[18];
  const float* pw2    = (const float*)d_in[19];
  const float* pb2    = (const float*)d_in[20];
  float* out = (float*)d_out;

  uint32_t k1a,k1b,k2a,k2b;
  tf_block(0u, 42u, 0u, 0u, &k1a, &k1b);   // keys[0]
  tf_block(0u, 42u, 0u, 1u, &k2a, &k2b);   // keys[1]

  static int smem_set = 0;
  if (!smem_set){
    cudaFuncSetAttribute(k_mlp, cudaFuncAttributeMaxDynamicSharedMemorySize,
                         MLP_SMEM_FLOATS*4);
    cudaFuncSetAttribute(k_conv, cudaFuncAttributeMaxDynamicSharedMemorySize,
                         CONV_SMEM_FLOATS*4);
    cudaFuncSetAttribute(k_conv, cudaFuncAttributePreferredSharedMemoryCarveout, 100);
    cudaFuncSetAttribute(k_spec, cudaFuncAttributePreferredSharedMemoryCarveout, 100);
    smem_set = 1;
  }

  k_wprep<<<144, 256>>>(cliffw);
  k_ln_spatial<<<256, 256>>>(x_real, x_imag, ln_s_g, ln_s_b);
  k_conv<<<dim3(32, 16), 256, CONV_SMEM_FLOATS*4>>>(cliffb);
  k_spec<<<512, 256>>>(specwr, specwi, gate, x_real, x_imag);
  k_ln_temporal<<<256, 256>>>(ln_t_g, ln_t_b);
  k_gates<<<1, 512>>>(dt, alpha, omega, gain_W, gain_b);
  k_scan<<<512, 256>>>(dt, sigma, k1a, k1b, k2a, k2b);
  k_mlp<<<512, 256, MLP_SMEM_FLOATS*4>>>(pw1, pb1, pw2, pb2, out);
}